// round 1
// baseline (speedup 1.0000x reference)
#include <cuda_runtime.h>
#include <math.h>

#define B_    8
#define N_    512
#define T_    64
#define NIN_  64
#define NEMB_ 128
#define NH_   128
#define ROWS_ (B_ * N_)
#define ZSTR  392   // padded z row stride (floats): 384 data + 8 pad, 16B-aligned rows

typedef unsigned long long u64;

// ---------------- device scratch (static globals: no runtime allocation) ----
__device__ float g_An[B_ * N_ * N_];        // normalized adjacency, 8 MB
__device__ float g_dinv[ROWS_];
__device__ float g_es[ROWS_ * NEMB_];       // source embedding (constant over steps)
__device__ float g_h[2][ROWS_ * NH_];       // double-buffered hidden state
__device__ float g_c[ROWS_ * NH_];          // cell state (updated in place, row-local)

// ---------------- packed f32x2 helpers (Blackwell FFMA2: 2x fp32 rate) ------
__device__ __forceinline__ u64 pk2(float x, float y) {
  u64 r; asm("mov.b64 %0, {%1, %2};" : "=l"(r) : "f"(x), "f"(y)); return r;
}
__device__ __forceinline__ u64 bc2(float x) { return pk2(x, x); }
__device__ __forceinline__ void up2(u64 v, float& x, float& y) {
  asm("mov.b64 {%0, %1}, %2;" : "=f"(x), "=f"(y) : "l"(v));
}
__device__ __forceinline__ void fma2(u64& d, u64 a, u64 b) {
  asm("fma.rn.f32x2 %0, %1, %2, %0;" : "+l"(d) : "l"(a), "l"(b));
}
__device__ __forceinline__ u64 add2(u64 a, u64 b) {
  u64 d; asm("add.rn.f32x2 %0, %1, %2;" : "=l"(d) : "l"(a), "l"(b)); return d;
}
__device__ __forceinline__ float sgm(float x) { return 1.0f / (1.0f + expf(-x)); }

// ---------------- preamble kernels ------------------------------------------
__global__ void k_dinv(const float* __restrict__ A) {
  int row = blockIdx.x;                 // b*512 + n
  const float* ap = A + (size_t)row * N_;
  float s = 0.0f;
  for (int m = threadIdx.x; m < N_; m += blockDim.x) s += ap[m];
  __shared__ float red[128];
  red[threadIdx.x] = s;
  __syncthreads();
  for (int off = 64; off; off >>= 1) {
    if (threadIdx.x < off) red[threadIdx.x] += red[threadIdx.x + off];
    __syncthreads();
  }
  if (threadIdx.x == 0) {
    float d = red[0];
    g_dinv[row] = (d > 0.0f) ? (1.0f / sqrtf(d)) : 0.0f;
  }
}

__global__ void k_an(const float* __restrict__ A) {
  size_t total = (size_t)B_ * N_ * N_;
  for (size_t i = blockIdx.x * (size_t)blockDim.x + threadIdx.x; i < total;
       i += (size_t)gridDim.x * blockDim.x) {
    int m = (int)(i & 511);
    size_t r = i >> 9;
    int n = (int)(r & 511);
    int b = (int)(r >> 9);
    g_An[i] = A[i] * g_dinv[b * N_ + n] * g_dinv[b * N_ + m];
  }
}

// es = X0 @ Wse + bse ; zero h0, c0 ; write output slice t=0
__global__ void k_init(const float* __restrict__ X, const float* __restrict__ Wse,
                       const float* __restrict__ bse, float* __restrict__ out) {
  int tid = blockIdx.x * blockDim.x + threadIdx.x;   // 0 .. ROWS_*NEMB_-1
  int row = tid >> 7;
  int c = tid & 127;
  const float* x0 = X + (size_t)row * (T_ * NIN_);   // X[b,n,0,:]
  float acc = bse[c];
  #pragma unroll 8
  for (int k = 0; k < NIN_; k++) acc += x0[k] * Wse[k * NEMB_ + c];
  g_es[(size_t)row * NEMB_ + c] = acc;
  g_h[0][tid] = 0.0f;
  g_c[tid] = 0.0f;
  if (c < NIN_) out[(size_t)row * (T_ * NIN_) + c] = x0[c];   // out[b,n,0,c] = X0
}

// ---------------- step kernel ----------------------------------------------
struct StepP {
  const float *Wpe, *bpe, *Wii, *bii, *Whi, *bhi, *Wif, *bif, *Whf, *bhf,
              *Wig, *big, *Whg, *bhg, *Wio, *bio, *Who, *bho, *Wout, *bout;
  float* out;
};

// pre-activation for one gate: pre = z[:,0:256]@Wx + z[:,256:384]@Wh + bx + bh
__device__ __forceinline__ void gate_pre(
    const float* zs, int rA, int rB, int c0,
    const float* __restrict__ Wx, const float* __restrict__ bx,
    const float* __restrict__ Wh, const float* __restrict__ bh,
    float oA[8], float oB[8]) {
  u64 acc[2][4];
  {
    const ulonglong2* bxp = (const ulonglong2*)(bx + c0);
    const ulonglong2* bhp = (const ulonglong2*)(bh + c0);
    ulonglong2 x01 = bxp[0], x23 = bxp[1];
    ulonglong2 h01 = bhp[0], h23 = bhp[1];
    acc[0][0] = add2(x01.x, h01.x); acc[0][1] = add2(x01.y, h01.y);
    acc[0][2] = add2(x23.x, h23.x); acc[0][3] = add2(x23.y, h23.y);
    acc[1][0] = acc[0][0]; acc[1][1] = acc[0][1];
    acc[1][2] = acc[0][2]; acc[1][3] = acc[0][3];
  }
  #pragma unroll 2
  for (int k = 0; k < 2 * NEMB_; k++) {
    u64 a0 = bc2(zs[rA * ZSTR + k]);
    u64 a1 = bc2(zs[rB * ZSTR + k]);
    const ulonglong2* wp = (const ulonglong2*)(Wx + k * NH_ + c0);
    ulonglong2 w01 = wp[0], w23 = wp[1];
    fma2(acc[0][0], a0, w01.x); fma2(acc[0][1], a0, w01.y);
    fma2(acc[0][2], a0, w23.x); fma2(acc[0][3], a0, w23.y);
    fma2(acc[1][0], a1, w01.x); fma2(acc[1][1], a1, w01.y);
    fma2(acc[1][2], a1, w23.x); fma2(acc[1][3], a1, w23.y);
  }
  #pragma unroll 2
  for (int k = 0; k < NH_; k++) {
    u64 a0 = bc2(zs[rA * ZSTR + 256 + k]);
    u64 a1 = bc2(zs[rB * ZSTR + 256 + k]);
    const ulonglong2* wp = (const ulonglong2*)(Wh + k * NH_ + c0);
    ulonglong2 w01 = wp[0], w23 = wp[1];
    fma2(acc[0][0], a0, w01.x); fma2(acc[0][1], a0, w01.y);
    fma2(acc[0][2], a0, w23.x); fma2(acc[0][3], a0, w23.y);
    fma2(acc[1][0], a1, w01.x); fma2(acc[1][1], a1, w01.y);
    fma2(acc[1][2], a1, w23.x); fma2(acc[1][3], a1, w23.y);
  }
  #pragma unroll
  for (int j = 0; j < 4; j++) {
    up2(acc[0][j], oA[2 * j], oA[2 * j + 1]);
    up2(acc[1][j], oB[2 * j], oB[2 * j + 1]);
  }
}

__global__ void __launch_bounds__(256, 1) k_step(StepP p, int t) {
  extern __shared__ float sm[];
  float* zs = sm;                       // [32][ZSTR]  (0:128 es | 128:256 eh | 256:384 h_prev)
  float* Hs = sm + 32 * ZSTR;           // [32][128]   H = An@h  (later reused for h_t)
  float* hs = Hs + 32 * NH_;            // [64][128]   h_prev k-chunk
  float* As = hs + 64 * NH_;            // [32][64]    An tile

  const float* hprev = g_h[(t - 1) & 1];
  float* hnext = g_h[t & 1];

  int b = blockIdx.y;
  int r0 = blockIdx.x * 32;
  int tid = threadIdx.x;
  int cblk = tid & 15;
  int rh = tid >> 4;                    // 0..15
  int c0 = cblk * 8;
  int rA = rh, rB = rh + 16;

  const float* esb = g_es + (size_t)(b * N_ + r0) * NEMB_;
  const float* hpb = hprev + (size_t)b * N_ * NH_;
  const float* hpr = hpb + (size_t)r0 * NH_;

  // stage z: es and h_prev parts
  for (int i = tid; i < 32 * 128; i += 256) {
    int r = i >> 7, c = i & 127;
    zs[r * ZSTR + c] = esb[r * NEMB_ + c];
    zs[r * ZSTR + 256 + c] = hpr[r * NH_ + c];
  }

  // ---- GEMM1: H[32x128] = An[r0:r0+32, :] @ h_prev[b]  (K = 512) ----
  u64 acc[2][4];
  #pragma unroll
  for (int rr = 0; rr < 2; rr++)
    #pragma unroll
    for (int j = 0; j < 4; j++) acc[rr][j] = 0ull;

  const float* Anb = g_An + (size_t)(b * N_ + r0) * N_;
  for (int k0 = 0; k0 < N_; k0 += 64) {
    __syncthreads();
    for (int i = tid; i < (64 * 128) / 4; i += 256) {
      int r = i >> 5, c4 = (i & 31) * 4;
      *(float4*)(hs + r * 128 + c4) = *(const float4*)(hpb + (size_t)(k0 + r) * NH_ + c4);
    }
    for (int i = tid; i < (32 * 64) / 4; i += 256) {
      int r = i >> 4, c4 = (i & 15) * 4;
      *(float4*)(As + r * 64 + c4) = *(const float4*)(Anb + (size_t)r * N_ + k0 + c4);
    }
    __syncthreads();
    #pragma unroll 4
    for (int kk = 0; kk < 64; kk++) {
      u64 a0 = bc2(As[rA * 64 + kk]);
      u64 a1 = bc2(As[rB * 64 + kk]);
      const ulonglong2* hp = (const ulonglong2*)(hs + kk * 128 + c0);
      ulonglong2 h01 = hp[0], h23 = hp[1];
      fma2(acc[0][0], a0, h01.x); fma2(acc[0][1], a0, h01.y);
      fma2(acc[0][2], a0, h23.x); fma2(acc[0][3], a0, h23.y);
      fma2(acc[1][0], a1, h01.x); fma2(acc[1][1], a1, h01.y);
      fma2(acc[1][2], a1, h23.x); fma2(acc[1][3], a1, h23.y);
    }
  }
  __syncthreads();
  {
    ulonglong2* d0 = (ulonglong2*)(Hs + rA * 128 + c0);
    d0[0] = make_ulonglong2(acc[0][0], acc[0][1]);
    d0[1] = make_ulonglong2(acc[0][2], acc[0][3]);
    ulonglong2* d1 = (ulonglong2*)(Hs + rB * 128 + c0);
    d1[0] = make_ulonglong2(acc[1][0], acc[1][1]);
    d1[1] = make_ulonglong2(acc[1][2], acc[1][3]);
  }
  __syncthreads();

  // ---- eh = H @ Wpe + bpe  -> zs[:,128:256] ----
  {
    const ulonglong2* bp = (const ulonglong2*)(p.bpe + c0);
    ulonglong2 b01 = bp[0], b23 = bp[1];
    acc[0][0] = b01.x; acc[0][1] = b01.y; acc[0][2] = b23.x; acc[0][3] = b23.y;
    acc[1][0] = b01.x; acc[1][1] = b01.y; acc[1][2] = b23.x; acc[1][3] = b23.y;
    #pragma unroll 2
    for (int k = 0; k < NH_; k++) {
      u64 a0 = bc2(Hs[rA * 128 + k]);
      u64 a1 = bc2(Hs[rB * 128 + k]);
      const ulonglong2* wp = (const ulonglong2*)(p.Wpe + k * NEMB_ + c0);
      ulonglong2 w01 = wp[0], w23 = wp[1];
      fma2(acc[0][0], a0, w01.x); fma2(acc[0][1], a0, w01.y);
      fma2(acc[0][2], a0, w23.x); fma2(acc[0][3], a0, w23.y);
      fma2(acc[1][0], a1, w01.x); fma2(acc[1][1], a1, w01.y);
      fma2(acc[1][2], a1, w23.x); fma2(acc[1][3], a1, w23.y);
    }
    ulonglong2* dA = (ulonglong2*)(zs + rA * ZSTR + 128 + c0);
    dA[0] = make_ulonglong2(acc[0][0], acc[0][1]);
    dA[1] = make_ulonglong2(acc[0][2], acc[0][3]);
    ulonglong2* dB = (ulonglong2*)(zs + rB * ZSTR + 128 + c0);
    dB[0] = make_ulonglong2(acc[1][0], acc[1][1]);
    dB[1] = make_ulonglong2(acc[1][2], acc[1][3]);
  }
  __syncthreads();

  // ---- LSTM gates (each thread: rows rA,rB x cols c0..c0+7) ----
  float preA[8], preB[8], cA[8], cB[8], iA[8], iB[8];
  float* crow = g_c + (size_t)(b * N_ + r0) * NH_;

  // f gate -> partial c = f * c_old
  gate_pre(zs, rA, rB, c0, p.Wif, p.bif, p.Whf, p.bhf, preA, preB);
  {
    float4 a0 = *(const float4*)(crow + rA * NH_ + c0);
    float4 a1 = *(const float4*)(crow + rA * NH_ + c0 + 4);
    float4 b0 = *(const float4*)(crow + rB * NH_ + c0);
    float4 b1 = *(const float4*)(crow + rB * NH_ + c0 + 4);
    float coA[8] = {a0.x, a0.y, a0.z, a0.w, a1.x, a1.y, a1.z, a1.w};
    float coB[8] = {b0.x, b0.y, b0.z, b0.w, b1.x, b1.y, b1.z, b1.w};
    #pragma unroll
    for (int j = 0; j < 8; j++) {
      cA[j] = sgm(preA[j]) * coA[j];
      cB[j] = sgm(preB[j]) * coB[j];
    }
  }
  // i gate
  gate_pre(zs, rA, rB, c0, p.Wii, p.bii, p.Whi, p.bhi, preA, preB);
  #pragma unroll
  for (int j = 0; j < 8; j++) { iA[j] = sgm(preA[j]); iB[j] = sgm(preB[j]); }
  // g gate -> c_new = f*c + i*tanh(pre_g)
  gate_pre(zs, rA, rB, c0, p.Wig, p.big, p.Whg, p.bhg, preA, preB);
  #pragma unroll
  for (int j = 0; j < 8; j++) {
    cA[j] += iA[j] * tanhf(preA[j]);
    cB[j] += iB[j] * tanhf(preB[j]);
  }
  *(float4*)(crow + rA * NH_ + c0)     = make_float4(cA[0], cA[1], cA[2], cA[3]);
  *(float4*)(crow + rA * NH_ + c0 + 4) = make_float4(cA[4], cA[5], cA[6], cA[7]);
  *(float4*)(crow + rB * NH_ + c0)     = make_float4(cB[0], cB[1], cB[2], cB[3]);
  *(float4*)(crow + rB * NH_ + c0 + 4) = make_float4(cB[4], cB[5], cB[6], cB[7]);
  // o gate -> h = o * tanh(c_new)
  gate_pre(zs, rA, rB, c0, p.Wio, p.bio, p.Who, p.bho, preA, preB);
  float hA[8], hB[8];
  #pragma unroll
  for (int j = 0; j < 8; j++) {
    hA[j] = sgm(preA[j]) * tanhf(cA[j]);
    hB[j] = sgm(preB[j]) * tanhf(cB[j]);
  }
  // store h to global state + smem (Hs reused; eh phase done reading it)
  {
    float* hnr = hnext + (size_t)(b * N_ + r0) * NH_;
    *(float4*)(hnr + rA * NH_ + c0)     = make_float4(hA[0], hA[1], hA[2], hA[3]);
    *(float4*)(hnr + rA * NH_ + c0 + 4) = make_float4(hA[4], hA[5], hA[6], hA[7]);
    *(float4*)(hnr + rB * NH_ + c0)     = make_float4(hB[0], hB[1], hB[2], hB[3]);
    *(float4*)(hnr + rB * NH_ + c0 + 4) = make_float4(hB[4], hB[5], hB[6], hB[7]);
    *(float4*)(Hs + rA * 128 + c0)      = make_float4(hA[0], hA[1], hA[2], hA[3]);
    *(float4*)(Hs + rA * 128 + c0 + 4)  = make_float4(hA[4], hA[5], hA[6], hA[7]);
    *(float4*)(Hs + rB * 128 + c0)      = make_float4(hB[0], hB[1], hB[2], hB[3]);
    *(float4*)(Hs + rB * 128 + c0 + 4)  = make_float4(hB[4], hB[5], hB[6], hB[7]);
  }
  __syncthreads();

  // ---- out[:,:,t,:] = out[:,:,t-1,:] + h @ Wout + bout ----
  {
    int co0 = cblk * 4;                      // 16 cblks x 4 cols = 64 output cols
    const ulonglong2* bp = (const ulonglong2*)(p.bout + co0);
    ulonglong2 bb = bp[0];
    u64 oa00 = bb.x, oa01 = bb.y, oa10 = bb.x, oa11 = bb.y;
    #pragma unroll 4
    for (int k = 0; k < NH_; k++) {
      u64 a0 = bc2(Hs[rA * 128 + k]);
      u64 a1 = bc2(Hs[rB * 128 + k]);
      const ulonglong2* wp = (const ulonglong2*)(p.Wout + k * NIN_ + co0);
      ulonglong2 ww = wp[0];
      fma2(oa00, a0, ww.x); fma2(oa01, a0, ww.y);
      fma2(oa10, a1, ww.x); fma2(oa11, a1, ww.y);
    }
    #pragma unroll
    for (int rr = 0; rr < 2; rr++) {
      int r = (rr ? rB : rA);
      size_t gb = (size_t)(b * N_ + r0 + r) * (T_ * NIN_);
      float4 prev = *(const float4*)(p.out + gb + (size_t)(t - 1) * NIN_ + co0);
      float x0, x1, x2, x3;
      if (rr == 0) { up2(oa00, x0, x1); up2(oa01, x2, x3); }
      else         { up2(oa10, x0, x1); up2(oa11, x2, x3); }
      float4 nw = make_float4(prev.x + x0, prev.y + x1, prev.z + x2, prev.w + x3);
      *(float4*)(p.out + gb + (size_t)t * NIN_ + co0) = nw;
    }
  }
}

// ---------------- host launch ----------------------------------------------
extern "C" void kernel_launch(void* const* d_in, const int* in_sizes, int n_in,
                              void* d_out, int out_size) {
  const float* X   = (const float*)d_in[0];
  const float* A   = (const float*)d_in[1];
  const float* Wse = (const float*)d_in[2];
  const float* bse = (const float*)d_in[3];
  StepP p;
  p.Wpe  = (const float*)d_in[4];  p.bpe  = (const float*)d_in[5];
  p.Wii  = (const float*)d_in[6];  p.bii  = (const float*)d_in[7];
  p.Whi  = (const float*)d_in[8];  p.bhi  = (const float*)d_in[9];
  p.Wif  = (const float*)d_in[10]; p.bif  = (const float*)d_in[11];
  p.Whf  = (const float*)d_in[12]; p.bhf  = (const float*)d_in[13];
  p.Wig  = (const float*)d_in[14]; p.big  = (const float*)d_in[15];
  p.Whg  = (const float*)d_in[16]; p.bhg  = (const float*)d_in[17];
  p.Wio  = (const float*)d_in[18]; p.bio  = (const float*)d_in[19];
  p.Who  = (const float*)d_in[20]; p.bho  = (const float*)d_in[21];
  p.Wout = (const float*)d_in[22]; p.bout = (const float*)d_in[23];
  p.out  = (float*)d_out;

  const int SMEM = (32 * ZSTR + 32 * NH_ + 64 * NH_ + 32 * 64) * 4;  // 107,520 B
  cudaFuncSetAttribute(k_step, cudaFuncAttributeMaxDynamicSharedMemorySize, SMEM);

  k_dinv<<<ROWS_, 128>>>(A);
  k_an<<<2048, 256>>>(A);
  k_init<<<2048, 256>>>(X, Wse, bse, p.out);
  for (int t = 1; t < T_; t++) {
    k_step<<<dim3(N_ / 32, B_), 256, SMEM>>>(p, t);
  }
}

// round 5
// speedup vs baseline: 3.2892x; 3.2892x over previous
#include <cuda_runtime.h>
#include <math.h>
#include <stdint.h>

#define B_    8
#define N_    512
#define T_    64
#define NIN_  64
#define NEMB_ 128
#define NH_   128
#define ROWS_ (B_ * N_)
#define ZSTR  392   // padded z row stride (floats)

typedef unsigned long long u64;

// ---------------- device scratch ----------------
__device__ float g_An[B_ * N_ * N_];
__device__ float g_dinv[ROWS_];
__device__ float g_es[ROWS_ * NEMB_];
__device__ float g_h[2][ROWS_ * NH_];
__device__ float g_c[ROWS_ * NH_];
__device__ float g_Wz[384 * 512];     // fused gate weights [k=384][col=4*128 (i|f|g|o)]
__device__ float g_bz[512];           // fused gate bias

// ---------------- packed f32x2 helpers ----------------
__device__ __forceinline__ u64 pk2(float x, float y) {
  u64 r; asm("mov.b64 %0, {%1, %2};" : "=l"(r) : "f"(x), "f"(y)); return r;
}
__device__ __forceinline__ u64 bc2(float x) { return pk2(x, x); }
__device__ __forceinline__ void up2(u64 v, float& x, float& y) {
  asm("mov.b64 {%0, %1}, %2;" : "=f"(x), "=f"(y) : "l"(v));
}
__device__ __forceinline__ void fma2(u64& d, u64 a, u64 b) {
  asm("fma.rn.f32x2 %0, %1, %2, %0;" : "+l"(d) : "l"(a), "l"(b));
}
// fast sigmoid (ex2/rcp approx: ~1e-7 err). tanh stays accurate (tanhf).
__device__ __forceinline__ float fsgm(float x) {
  float e; asm("ex2.approx.f32 %0, %1;" : "=f"(e) : "f"(-1.4426950408889634f * x));
  float r; asm("rcp.approx.f32 %0, %1;" : "=f"(r) : "f"(1.0f + e));
  return r;
}
// cp.async
__device__ __forceinline__ uint32_t s2u(const void* p) {
  return (uint32_t)__cvta_generic_to_shared(p);
}
__device__ __forceinline__ void cp16(uint32_t d, const void* s) {
  asm volatile("cp.async.cg.shared.global [%0], [%1], 16;\n" :: "r"(d), "l"(s));
}
__device__ __forceinline__ void cpcommit() { asm volatile("cp.async.commit_group;\n"); }
template <int N> __device__ __forceinline__ void cpwait() {
  asm volatile("cp.async.wait_group %0;\n" :: "n"(N));
}

// ---------------- preamble kernels ----------------
__global__ void k_dinv(const float* __restrict__ A) {
  int row = blockIdx.x;
  const float* ap = A + (size_t)row * N_;
  float s = 0.0f;
  for (int m = threadIdx.x; m < N_; m += blockDim.x) s += ap[m];
  __shared__ float red[128];
  red[threadIdx.x] = s;
  __syncthreads();
  for (int off = 64; off; off >>= 1) {
    if (threadIdx.x < off) red[threadIdx.x] += red[threadIdx.x + off];
    __syncthreads();
  }
  if (threadIdx.x == 0) {
    float d = red[0];
    g_dinv[row] = (d > 0.0f) ? (1.0f / sqrtf(d)) : 0.0f;
  }
}

__global__ void k_an(const float* __restrict__ A) {
  size_t total = (size_t)B_ * N_ * N_;
  for (size_t i = blockIdx.x * (size_t)blockDim.x + threadIdx.x; i < total;
       i += (size_t)gridDim.x * blockDim.x) {
    int m = (int)(i & 511);
    size_t r = i >> 9;
    int n = (int)(r & 511);
    int b = (int)(r >> 9);
    g_An[i] = A[i] * g_dinv[b * N_ + n] * g_dinv[b * N_ + m];
  }
}

__global__ void k_init(const float* __restrict__ X, const float* __restrict__ Wse,
                       const float* __restrict__ bse, float* __restrict__ out) {
  int tid = blockIdx.x * blockDim.x + threadIdx.x;
  int row = tid >> 7;
  int c = tid & 127;
  const float* x0 = X + (size_t)row * (T_ * NIN_);
  float acc = bse[c];
  #pragma unroll 8
  for (int k = 0; k < NIN_; k++) acc += x0[k] * Wse[k * NEMB_ + c];
  g_es[(size_t)row * NEMB_ + c] = acc;
  g_h[0][tid] = 0.0f;
  g_c[tid] = 0.0f;
  if (c < NIN_) out[(size_t)row * (T_ * NIN_) + c] = x0[c];
}

struct StepP {
  const float *Wpe, *bpe, *Wii, *bii, *Whi, *bhi, *Wif, *bif, *Whf, *bhf,
              *Wig, *big, *Whg, *bhg, *Wio, *bio, *Who, *bho, *Wout, *bout;
  float* out;
};

__global__ void k_fuse(StepP p) {
  int i = blockIdx.x * blockDim.x + threadIdx.x;
  if (i < 384 * 512) {
    int c = i & 511, r = i >> 9, q = c >> 7, cc = c & 127;
    const float* W;
    if (r < 256)
      W = (q == 0 ? p.Wii : q == 1 ? p.Wif : q == 2 ? p.Wig : p.Wio) + r * 128;
    else
      W = (q == 0 ? p.Whi : q == 1 ? p.Whf : q == 2 ? p.Whg : p.Who) + (r - 256) * 128;
    g_Wz[i] = W[cc];
  }
  if (i < 512) {
    int q = i >> 7, cc = i & 127;
    const float* bx = q == 0 ? p.bii : q == 1 ? p.bif : q == 2 ? p.big : p.bio;
    const float* bh = q == 0 ? p.bhi : q == 1 ? p.bhf : q == 2 ? p.bhg : p.bho;
    g_bz[i] = bx[cc] + bh[cc];
  }
}

// ---------------- step kernel ----------------
// smem float offsets
#define SM_ZS   0                  // 32 x ZSTR = 12544
#define SM_HS   12544              // 32 x 128  = 4096
#define SM_BUFA 16640              // hs[2][64*128]=16384 + As[2][32*64]=4096 -> 20480 ; later Wout[128*64]=8192
#define SM_BUFB 37120              // WpeS[128*128]=16384 ; later Wz[2][16*512]=16384
#define SM_TOTF 53504              // floats (214,016 B)

__global__ void __launch_bounds__(256, 1) k_step(StepP p, int t) {
  extern __shared__ float sm[];
  float* zs    = sm + SM_ZS;    // [32][ZSTR]: 0:128 es | 128:256 eh | 256:384 h_prev
  float* Hs    = sm + SM_HS;    // [32][128] H, later h_t
  float* hsbuf = sm + SM_BUFA;              // [2][64*128]
  float* Asbuf = sm + SM_BUFA + 16384;      // [2][32*64]
  float* WoutS = sm + SM_BUFA;              // [128][64] (aliases hsbuf after GEMM1)
  float* WpeS  = sm + SM_BUFB;              // [128][128]
  float* WzS   = sm + SM_BUFB;              // [2][16*512] (aliases WpeS after eh)

  const float* hprev = g_h[(t - 1) & 1];
  float* hnext = g_h[t & 1];

  const int b = blockIdx.y;
  const int r0 = blockIdx.x * 32;
  const int tid = threadIdx.x;

  const float* esb = g_es + (size_t)(b * N_ + r0) * NEMB_;
  const float* hpb = hprev + (size_t)b * N_ * NH_;
  const float* hpr = hpb + (size_t)r0 * NH_;
  const float* Anb = g_An + (size_t)(b * N_ + r0) * N_;

  // --- group 1: zs (es + h_prev slice) ---
  #pragma unroll
  for (int j = 0; j < 4; j++) {
    int idx = tid + j * 256;
    int r = idx >> 5, c4 = (idx & 31) * 4;
    cp16(s2u(zs + r * ZSTR + c4), esb + r * NEMB_ + c4);
    cp16(s2u(zs + r * ZSTR + 256 + c4), hpr + r * NH_ + c4);
  }
  cpcommit();
  // --- group 2: Wpe stage ---
  #pragma unroll
  for (int j = 0; j < 16; j++) {
    int idx = tid + j * 256;
    int r = idx >> 5, c4 = (idx & 31) * 4;
    cp16(s2u(WpeS + r * 128 + c4), p.Wpe + r * 128 + c4);
  }
  cpcommit();

  // --- GEMM1: H[32x128] = An_tile @ h_prev, K=512, chunks of 64 ---
  const int rA = tid >> 4, rB = (tid >> 4) + 16;
  const int cblk = tid & 15;

  // prefetch chunk 0
  {
    #pragma unroll
    for (int j = 0; j < 8; j++) {
      int idx = tid + j * 256;
      int r = idx >> 5, c4 = (idx & 31) * 4;
      cp16(s2u(hsbuf + r * 128 + c4), hpb + (size_t)r * NH_ + c4);
    }
    #pragma unroll
    for (int j = 0; j < 2; j++) {
      int idx = tid + j * 256;
      int r = idx >> 4, k4 = (idx & 15) * 4;
      cp16(s2u(Asbuf + r * 64 + k4), Anb + (size_t)r * N_ + k4);
    }
  }
  cpcommit();

  u64 aH[2][2][2];
  #pragma unroll
  for (int i = 0; i < 2; i++)
    #pragma unroll
    for (int j = 0; j < 2; j++) { aH[i][j][0] = 0ull; aH[i][j][1] = 0ull; }

  #pragma unroll 1
  for (int ch = 0; ch < 8; ch++) {
    if (ch < 7) {
      int nb = (ch + 1) & 1;
      int k0 = (ch + 1) * 64;
      #pragma unroll
      for (int j = 0; j < 8; j++) {
        int idx = tid + j * 256;
        int r = idx >> 5, c4 = (idx & 31) * 4;
        cp16(s2u(hsbuf + nb * 8192 + r * 128 + c4), hpb + (size_t)(k0 + r) * NH_ + c4);
      }
      #pragma unroll
      for (int j = 0; j < 2; j++) {
        int idx = tid + j * 256;
        int r = idx >> 4, k4 = (idx & 15) * 4;
        cp16(s2u(Asbuf + nb * 2048 + r * 64 + k4), Anb + (size_t)r * N_ + k0 + k4);
      }
      cpcommit();
      cpwait<1>();
    } else {
      cpwait<0>();
    }
    __syncthreads();
    const float* hc = hsbuf + (ch & 1) * 8192;
    const float* Ac = Asbuf + (ch & 1) * 2048;
    #pragma unroll 4
    for (int kk = 0; kk < 64; kk += 4) {
      float4 a0v = *(const float4*)(Ac + rA * 64 + kk);
      float4 a1v = *(const float4*)(Ac + rB * 64 + kk);
      float a0c[4] = {a0v.x, a0v.y, a0v.z, a0v.w};
      float a1c[4] = {a1v.x, a1v.y, a1v.z, a1v.w};
      #pragma unroll
      for (int s = 0; s < 4; s++) {
        u64 A0 = bc2(a0c[s]), A1 = bc2(a1c[s]);
        const float* hrow = hc + (kk + s) * 128 + cblk * 4;
        ulonglong2 w0 = *(const ulonglong2*)(hrow);
        ulonglong2 w1 = *(const ulonglong2*)(hrow + 64);
        fma2(aH[0][0][0], A0, w0.x); fma2(aH[0][0][1], A0, w0.y);
        fma2(aH[0][1][0], A0, w1.x); fma2(aH[0][1][1], A0, w1.y);
        fma2(aH[1][0][0], A1, w0.x); fma2(aH[1][0][1], A1, w0.y);
        fma2(aH[1][1][0], A1, w1.x); fma2(aH[1][1][1], A1, w1.y);
      }
    }
    __syncthreads();
  }

  // store H to Hs
  {
    float4 v;
    up2(aH[0][0][0], v.x, v.y); up2(aH[0][0][1], v.z, v.w);
    *(float4*)(Hs + rA * 128 + cblk * 4) = v;
    up2(aH[0][1][0], v.x, v.y); up2(aH[0][1][1], v.z, v.w);
    *(float4*)(Hs + rA * 128 + 64 + cblk * 4) = v;
    up2(aH[1][0][0], v.x, v.y); up2(aH[1][0][1], v.z, v.w);
    *(float4*)(Hs + rB * 128 + cblk * 4) = v;
    up2(aH[1][1][0], v.x, v.y); up2(aH[1][1][1], v.z, v.w);
    *(float4*)(Hs + rB * 128 + 64 + cblk * 4) = v;
  }
  // prefetch Wout into bufA (GEMM1 done with it)
  #pragma unroll
  for (int j = 0; j < 8; j++) {
    int idx = tid + j * 256;
    int r = idx >> 4, c4 = (idx & 15) * 4;
    cp16(s2u(WoutS + r * 64 + c4), p.Wout + r * 64 + c4);
  }
  cpcommit();
  __syncthreads();

  // --- eh = H @ Wpe + bpe -> zs[:,128:256] ---
  {
    u64 aE[2][2][2];
    ulonglong2 b0 = *(const ulonglong2*)(p.bpe + cblk * 4);
    ulonglong2 b1 = *(const ulonglong2*)(p.bpe + 64 + cblk * 4);
    aE[0][0][0] = b0.x; aE[0][0][1] = b0.y; aE[0][1][0] = b1.x; aE[0][1][1] = b1.y;
    aE[1][0][0] = b0.x; aE[1][0][1] = b0.y; aE[1][1][0] = b1.x; aE[1][1][1] = b1.y;
    #pragma unroll 4
    for (int k = 0; k < 128; k += 4) {
      float4 a0v = *(const float4*)(Hs + rA * 128 + k);
      float4 a1v = *(const float4*)(Hs + rB * 128 + k);
      float a0c[4] = {a0v.x, a0v.y, a0v.z, a0v.w};
      float a1c[4] = {a1v.x, a1v.y, a1v.z, a1v.w};
      #pragma unroll
      for (int s = 0; s < 4; s++) {
        u64 A0 = bc2(a0c[s]), A1 = bc2(a1c[s]);
        const float* wrow = WpeS + (k + s) * 128 + cblk * 4;
        ulonglong2 w0 = *(const ulonglong2*)(wrow);
        ulonglong2 w1 = *(const ulonglong2*)(wrow + 64);
        fma2(aE[0][0][0], A0, w0.x); fma2(aE[0][0][1], A0, w0.y);
        fma2(aE[0][1][0], A0, w1.x); fma2(aE[0][1][1], A0, w1.y);
        fma2(aE[1][0][0], A1, w0.x); fma2(aE[1][0][1], A1, w0.y);
        fma2(aE[1][1][0], A1, w1.x); fma2(aE[1][1][1], A1, w1.y);
      }
    }
    float4 v;
    up2(aE[0][0][0], v.x, v.y); up2(aE[0][0][1], v.z, v.w);
    *(float4*)(zs + rA * ZSTR + 128 + cblk * 4) = v;
    up2(aE[0][1][0], v.x, v.y); up2(aE[0][1][1], v.z, v.w);
    *(float4*)(zs + rA * ZSTR + 192 + cblk * 4) = v;
    up2(aE[1][0][0], v.x, v.y); up2(aE[1][0][1], v.z, v.w);
    *(float4*)(zs + rB * ZSTR + 128 + cblk * 4) = v;
    up2(aE[1][1][0], v.x, v.y); up2(aE[1][1][1], v.z, v.w);
    *(float4*)(zs + rB * ZSTR + 192 + cblk * 4) = v;
  }
  __syncthreads();   // eh visible; WpeS free for Wz reuse

  // --- gates: pre[32x512] = z[32x384] @ Wz + bz, chunks of 16 k ---
  const int rowg = tid >> 5;       // warp id: 8 warps x 4 rows
  const int colg = tid & 31;       // lane: 4-col chunks per gate
  const int zr = rowg * 4;

  u64 ag[4][4][2];
  #pragma unroll
  for (int q = 0; q < 4; q++) {
    ulonglong2 bb = *(const ulonglong2*)(g_bz + q * 128 + colg * 4);
    #pragma unroll
    for (int j = 0; j < 4; j++) { ag[j][q][0] = bb.x; ag[j][q][1] = bb.y; }
  }

  // prefetch gate chunk 0
  #pragma unroll
  for (int j = 0; j < 8; j++) {
    int idx = tid + j * 256;
    int r = idx >> 7, c4 = (idx & 127) * 4;
    cp16(s2u(WzS + r * 512 + c4), g_Wz + r * 512 + c4);
  }
  cpcommit();

  #pragma unroll 1
  for (int ch = 0; ch < 24; ch++) {
    if (ch < 23) {
      int nb = (ch + 1) & 1;
      int k0 = (ch + 1) * 16;
      #pragma unroll
      for (int j = 0; j < 8; j++) {
        int idx = tid + j * 256;
        int r = idx >> 7, c4 = (idx & 127) * 4;
        cp16(s2u(WzS + nb * 8192 + r * 512 + c4), g_Wz + (size_t)(k0 + r) * 512 + c4);
      }
      cpcommit();
      cpwait<1>();
    } else {
      cpwait<0>();
    }
    __syncthreads();
    const float* Wc = WzS + (ch & 1) * 8192;
    const int kb = ch * 16;
    #pragma unroll 1
    for (int kk = 0; kk < 16; kk += 4) {
      float4 z0 = *(const float4*)(zs + (zr + 0) * ZSTR + kb + kk);
      float4 z1 = *(const float4*)(zs + (zr + 1) * ZSTR + kb + kk);
      float4 z2 = *(const float4*)(zs + (zr + 2) * ZSTR + kb + kk);
      float4 z3 = *(const float4*)(zs + (zr + 3) * ZSTR + kb + kk);
      float c0a[4] = {z0.x, z0.y, z0.z, z0.w};
      float c1a[4] = {z1.x, z1.y, z1.z, z1.w};
      float c2a[4] = {z2.x, z2.y, z2.z, z2.w};
      float c3a[4] = {z3.x, z3.y, z3.z, z3.w};
      #pragma unroll
      for (int s = 0; s < 4; s++) {
        u64 A0 = bc2(c0a[s]), A1 = bc2(c1a[s]), A2 = bc2(c2a[s]), A3 = bc2(c3a[s]);
        const float* wrow = Wc + (kk + s) * 512 + colg * 4;
        #pragma unroll
        for (int q = 0; q < 4; q++) {
          ulonglong2 w = *(const ulonglong2*)(wrow + q * 128);
          fma2(ag[0][q][0], A0, w.x); fma2(ag[0][q][1], A0, w.y);
          fma2(ag[1][q][0], A1, w.x); fma2(ag[1][q][1], A1, w.y);
          fma2(ag[2][q][0], A2, w.x); fma2(ag[2][q][1], A2, w.y);
          fma2(ag[3][q][0], A3, w.x); fma2(ag[3][q][1], A3, w.y);
        }
      }
    }
    __syncthreads();
  }

  // --- pointwise LSTM (gate order q: 0=i,1=f,2=g,3=o) ---
  {
    const int rowbase = b * N_ + r0 + zr;
    #pragma unroll
    for (int j = 0; j < 4; j++) {
      float pre[4][4];
      #pragma unroll
      for (int q = 0; q < 4; q++) {
        up2(ag[j][q][0], pre[q][0], pre[q][1]);
        up2(ag[j][q][1], pre[q][2], pre[q][3]);
      }
      float* crow = g_c + (size_t)(rowbase + j) * NH_ + colg * 4;
      float4 co = *(const float4*)crow;
      float cin[4] = {co.x, co.y, co.z, co.w};
      float cn[4], hh[4];
      #pragma unroll
      for (int pp = 0; pp < 4; pp++) {
        float iv = fsgm(pre[0][pp]);
        float fv = fsgm(pre[1][pp]);
        float gv = tanhf(pre[2][pp]);
        float ov = fsgm(pre[3][pp]);
        cn[pp] = fv * cin[pp] + iv * gv;
        hh[pp] = ov * tanhf(cn[pp]);
      }
      *(float4*)crow = make_float4(cn[0], cn[1], cn[2], cn[3]);
      float4 hv = make_float4(hh[0], hh[1], hh[2], hh[3]);
      *(float4*)(hnext + (size_t)(rowbase + j) * NH_ + colg * 4) = hv;
      *(float4*)(Hs + (zr + j) * 128 + colg * 4) = hv;
    }
  }
  __syncthreads();

  // --- out[t] = out[t-1] + h @ Wout + bout ---
  {
    u64 ao[2][2];
    ulonglong2 bb = *(const ulonglong2*)(p.bout + cblk * 4);
    ao[0][0] = bb.x; ao[0][1] = bb.y; ao[1][0] = bb.x; ao[1][1] = bb.y;
    #pragma unroll 4
    for (int k = 0; k < 128; k += 4) {
      float4 a0v = *(const float4*)(Hs + rA * 128 + k);
      float4 a1v = *(const float4*)(Hs + rB * 128 + k);
      float a0c[4] = {a0v.x, a0v.y, a0v.z, a0v.w};
      float a1c[4] = {a1v.x, a1v.y, a1v.z, a1v.w};
      #pragma unroll
      for (int s = 0; s < 4; s++) {
        u64 A0 = bc2(a0c[s]), A1 = bc2(a1c[s]);
        ulonglong2 w = *(const ulonglong2*)(WoutS + (k + s) * 64 + cblk * 4);
        fma2(ao[0][0], A0, w.x); fma2(ao[0][1], A0, w.y);
        fma2(ao[1][0], A1, w.x); fma2(ao[1][1], A1, w.y);
      }
    }
    #pragma unroll
    for (int rr = 0; rr < 2; rr++) {
      int r = (rr ? rB : rA);
      size_t gb = (size_t)(b * N_ + r0 + r) * (T_ * NIN_);
      float4 prev = *(const float4*)(p.out + gb + (size_t)(t - 1) * NIN_ + cblk * 4);
      float x0, x1, x2, x3;
      up2(ao[rr][0], x0, x1); up2(ao[rr][1], x2, x3);
      *(float4*)(p.out + gb + (size_t)t * NIN_ + cblk * 4) =
          make_float4(prev.x + x0, prev.y + x1, prev.z + x2, prev.w + x3);
    }
  }
}

// ---------------- host launch ----------------
extern "C" void kernel_launch(void* const* d_in, const int* in_sizes, int n_in,
                              void* d_out, int out_size) {
  const float* X   = (const float*)d_in[0];
  const float* A   = (const float*)d_in[1];
  const float* Wse = (const float*)d_in[2];
  const float* bse = (const float*)d_in[3];
  StepP p;
  p.Wpe  = (const float*)d_in[4];  p.bpe  = (const float*)d_in[5];
  p.Wii  = (const float*)d_in[6];  p.bii  = (const float*)d_in[7];
  p.Whi  = (const float*)d_in[8];  p.bhi  = (const float*)d_in[9];
  p.Wif  = (const float*)d_in[10]; p.bif  = (const float*)d_in[11];
  p.Whf  = (const float*)d_in[12]; p.bhf  = (const float*)d_in[13];
  p.Wig  = (const float*)d_in[14]; p.big  = (const float*)d_in[15];
  p.Whg  = (const float*)d_in[16]; p.bhg  = (const float*)d_in[17];
  p.Wio  = (const float*)d_in[18]; p.bio  = (const float*)d_in[19];
  p.Who  = (const float*)d_in[20]; p.bho  = (const float*)d_in[21];
  p.Wout = (const float*)d_in[22]; p.bout = (const float*)d_in[23];
  p.out  = (float*)d_out;

  const int SMEM = SM_TOTF * 4;  // 214,016 B
  cudaFuncSetAttribute(k_step, cudaFuncAttributeMaxDynamicSharedMemorySize, SMEM);

  k_dinv<<<ROWS_, 128>>>(A);
  k_an<<<2048, 256>>>(A);
  k_fuse<<<768, 256>>>(p);
  k_init<<<2048, 256>>>(X, Wse, bse, p.out);
  for (int t = 1; t < T_; t++) {
    k_step<<<dim3(N_ / 32, B_), 256, SMEM>>>(p, t);
  }
}

// round 6
// speedup vs baseline: 3.2919x; 1.0008x over previous
#include <cuda_runtime.h>
#include <math.h>
#include <stdint.h>

#define B_    8
#define N_    512
#define T_    64
#define NIN_  64
#define NEMB_ 128
#define NH_   128
#define ROWS_ (B_ * N_)
#define ZSTR  392   // padded z row stride (floats)

typedef unsigned long long u64;

// ---------------- device scratch ----------------
__device__ float g_An[B_ * N_ * N_];
__device__ float g_dinv[ROWS_];
__device__ float g_es[ROWS_ * NEMB_];
__device__ float g_h[2][ROWS_ * NH_];
__device__ float g_c[ROWS_ * NH_];
__device__ float g_Wz[384 * 512];     // fused gate weights [k=384][col=4*128 (i|f|g|o)]
__device__ float g_bz[512];           // fused gate bias

// ---------------- packed f32x2 helpers ----------------
__device__ __forceinline__ u64 pk2(float x, float y) {
  u64 r; asm("mov.b64 %0, {%1, %2};" : "=l"(r) : "f"(x), "f"(y)); return r;
}
__device__ __forceinline__ u64 bc2(float x) { return pk2(x, x); }
__device__ __forceinline__ void up2(u64 v, float& x, float& y) {
  asm("mov.b64 {%0, %1}, %2;" : "=f"(x), "=f"(y) : "l"(v));
}
__device__ __forceinline__ void fma2(u64& d, u64 a, u64 b) {
  asm("fma.rn.f32x2 %0, %1, %2, %0;" : "+l"(d) : "l"(a), "l"(b));
}
// fast sigmoid (ex2/rcp approx: ~1e-7 err). tanh stays accurate (tanhf).
__device__ __forceinline__ float fsgm(float x) {
  float e; asm("ex2.approx.f32 %0, %1;" : "=f"(e) : "f"(-1.4426950408889634f * x));
  float r; asm("rcp.approx.f32 %0, %1;" : "=f"(r) : "f"(1.0f + e));
  return r;
}
// cp.async
__device__ __forceinline__ uint32_t s2u(const void* p) {
  return (uint32_t)__cvta_generic_to_shared(p);
}
__device__ __forceinline__ void cp16(uint32_t d, const void* s) {
  asm volatile("cp.async.cg.shared.global [%0], [%1], 16;\n" :: "r"(d), "l"(s));
}
__device__ __forceinline__ void cpcommit() { asm volatile("cp.async.commit_group;\n"); }
template <int N> __device__ __forceinline__ void cpwait() {
  asm volatile("cp.async.wait_group %0;\n" :: "n"(N));
}

// ---------------- preamble kernels ----------------
__global__ void k_dinv(const float* __restrict__ A) {
  int row = blockIdx.x;
  const float* ap = A + (size_t)row * N_;
  float s = 0.0f;
  for (int m = threadIdx.x; m < N_; m += blockDim.x) s += ap[m];
  __shared__ float red[128];
  red[threadIdx.x] = s;
  __syncthreads();
  for (int off = 64; off; off >>= 1) {
    if (threadIdx.x < off) red[threadIdx.x] += red[threadIdx.x + off];
    __syncthreads();
  }
  if (threadIdx.x == 0) {
    float d = red[0];
    g_dinv[row] = (d > 0.0f) ? (1.0f / sqrtf(d)) : 0.0f;
  }
}

__global__ void k_an(const float* __restrict__ A) {
  size_t total = (size_t)B_ * N_ * N_;
  for (size_t i = blockIdx.x * (size_t)blockDim.x + threadIdx.x; i < total;
       i += (size_t)gridDim.x * blockDim.x) {
    int m = (int)(i & 511);
    size_t r = i >> 9;
    int n = (int)(r & 511);
    int b = (int)(r >> 9);
    g_An[i] = A[i] * g_dinv[b * N_ + n] * g_dinv[b * N_ + m];
  }
}

__global__ void k_init(const float* __restrict__ X, const float* __restrict__ Wse,
                       const float* __restrict__ bse, float* __restrict__ out) {
  int tid = blockIdx.x * blockDim.x + threadIdx.x;
  int row = tid >> 7;
  int c = tid & 127;
  const float* x0 = X + (size_t)row * (T_ * NIN_);
  float acc = bse[c];
  #pragma unroll 8
  for (int k = 0; k < NIN_; k++) acc += x0[k] * Wse[k * NEMB_ + c];
  g_es[(size_t)row * NEMB_ + c] = acc;
  g_h[0][tid] = 0.0f;
  g_c[tid] = 0.0f;
  if (c < NIN_) out[(size_t)row * (T_ * NIN_) + c] = x0[c];
}

struct StepP {
  const float *Wpe, *bpe, *Wii, *bii, *Whi, *bhi, *Wif, *bif, *Whf, *bhf,
              *Wig, *big, *Whg, *bhg, *Wio, *bio, *Who, *bho, *Wout, *bout;
  float* out;
};

__global__ void k_fuse(StepP p) {
  int i = blockIdx.x * blockDim.x + threadIdx.x;
  if (i < 384 * 512) {
    int c = i & 511, r = i >> 9, q = c >> 7, cc = c & 127;
    const float* W;
    if (r < 256)
      W = (q == 0 ? p.Wii : q == 1 ? p.Wif : q == 2 ? p.Wig : p.Wio) + r * 128;
    else
      W = (q == 0 ? p.Whi : q == 1 ? p.Whf : q == 2 ? p.Whg : p.Who) + (r - 256) * 128;
    g_Wz[i] = W[cc];
  }
  if (i < 512) {
    int q = i >> 7, cc = i & 127;
    const float* bx = q == 0 ? p.bii : q == 1 ? p.bif : q == 2 ? p.big : p.bio;
    const float* bh = q == 0 ? p.bhi : q == 1 ? p.bhf : q == 2 ? p.bhg : p.bho;
    g_bz[i] = bx[cc] + bh[cc];
  }
}

// ---------------- step kernel ----------------
// smem float offsets
#define SM_ZS   0                  // 32 x ZSTR = 12544
#define SM_HS   12544              // 32 x 128  = 4096
#define SM_BUFA 16640              // hs[2][64*128]=16384 + As[2][32*64]=4096 -> 20480 ; later Wout[128*64]=8192
#define SM_BUFB 37120              // WpeS[128*128]=16384 ; later Wz[2][16*512]=16384
#define SM_TOTF 53504              // floats (214,016 B)

__global__ void __launch_bounds__(256, 1) k_step(StepP p, int t) {
  extern __shared__ float sm[];
  float* zs    = sm + SM_ZS;    // [32][ZSTR]: 0:128 es | 128:256 eh | 256:384 h_prev
  float* Hs    = sm + SM_HS;    // [32][128] H, later h_t
  float* hsbuf = sm + SM_BUFA;              // [2][64*128]
  float* Asbuf = sm + SM_BUFA + 16384;      // [2][32*64]
  float* WoutS = sm + SM_BUFA;              // [128][64] (aliases hsbuf after GEMM1)
  float* WpeS  = sm + SM_BUFB;              // [128][128]
  float* WzS   = sm + SM_BUFB;              // [2][16*512] (aliases WpeS after eh)

  const float* hprev = g_h[(t - 1) & 1];
  float* hnext = g_h[t & 1];

  const int b = blockIdx.y;
  const int r0 = blockIdx.x * 32;
  const int tid = threadIdx.x;

  const float* esb = g_es + (size_t)(b * N_ + r0) * NEMB_;
  const float* hpb = hprev + (size_t)b * N_ * NH_;
  const float* hpr = hpb + (size_t)r0 * NH_;
  const float* Anb = g_An + (size_t)(b * N_ + r0) * N_;

  // --- group 1: zs (es + h_prev slice) ---
  #pragma unroll
  for (int j = 0; j < 4; j++) {
    int idx = tid + j * 256;
    int r = idx >> 5, c4 = (idx & 31) * 4;
    cp16(s2u(zs + r * ZSTR + c4), esb + r * NEMB_ + c4);
    cp16(s2u(zs + r * ZSTR + 256 + c4), hpr + r * NH_ + c4);
  }
  cpcommit();
  // --- group 2: Wpe stage ---
  #pragma unroll
  for (int j = 0; j < 16; j++) {
    int idx = tid + j * 256;
    int r = idx >> 5, c4 = (idx & 31) * 4;
    cp16(s2u(WpeS + r * 128 + c4), p.Wpe + r * 128 + c4);
  }
  cpcommit();

  // --- GEMM1: H[32x128] = An_tile @ h_prev, K=512, chunks of 64 ---
  const int rA = tid >> 4, rB = (tid >> 4) + 16;
  const int cblk = tid & 15;

  // prefetch chunk 0
  {
    #pragma unroll
    for (int j = 0; j < 8; j++) {
      int idx = tid + j * 256;
      int r = idx >> 5, c4 = (idx & 31) * 4;
      cp16(s2u(hsbuf + r * 128 + c4), hpb + (size_t)r * NH_ + c4);
    }
    #pragma unroll
    for (int j = 0; j < 2; j++) {
      int idx = tid + j * 256;
      int r = idx >> 4, k4 = (idx & 15) * 4;
      cp16(s2u(Asbuf + r * 64 + k4), Anb + (size_t)r * N_ + k4);
    }
  }
  cpcommit();

  u64 aH[2][2][2];
  #pragma unroll
  for (int i = 0; i < 2; i++)
    #pragma unroll
    for (int j = 0; j < 2; j++) { aH[i][j][0] = 0ull; aH[i][j][1] = 0ull; }

  #pragma unroll 1
  for (int ch = 0; ch < 8; ch++) {
    if (ch < 7) {
      int nb = (ch + 1) & 1;
      int k0 = (ch + 1) * 64;
      #pragma unroll
      for (int j = 0; j < 8; j++) {
        int idx = tid + j * 256;
        int r = idx >> 5, c4 = (idx & 31) * 4;
        cp16(s2u(hsbuf + nb * 8192 + r * 128 + c4), hpb + (size_t)(k0 + r) * NH_ + c4);
      }
      #pragma unroll
      for (int j = 0; j < 2; j++) {
        int idx = tid + j * 256;
        int r = idx >> 4, k4 = (idx & 15) * 4;
        cp16(s2u(Asbuf + nb * 2048 + r * 64 + k4), Anb + (size_t)r * N_ + k0 + k4);
      }
      cpcommit();
      cpwait<1>();
    } else {
      cpwait<0>();
    }
    __syncthreads();
    const float* hc = hsbuf + (ch & 1) * 8192;
    const float* Ac = Asbuf + (ch & 1) * 2048;
    #pragma unroll 4
    for (int kk = 0; kk < 64; kk += 4) {
      float4 a0v = *(const float4*)(Ac + rA * 64 + kk);
      float4 a1v = *(const float4*)(Ac + rB * 64 + kk);
      float a0c[4] = {a0v.x, a0v.y, a0v.z, a0v.w};
      float a1c[4] = {a1v.x, a1v.y, a1v.z, a1v.w};
      #pragma unroll
      for (int s = 0; s < 4; s++) {
        u64 A0 = bc2(a0c[s]), A1 = bc2(a1c[s]);
        const float* hrow = hc + (kk + s) * 128 + cblk * 4;
        ulonglong2 w0 = *(const ulonglong2*)(hrow);
        ulonglong2 w1 = *(const ulonglong2*)(hrow + 64);
        fma2(aH[0][0][0], A0, w0.x); fma2(aH[0][0][1], A0, w0.y);
        fma2(aH[0][1][0], A0, w1.x); fma2(aH[0][1][1], A0, w1.y);
        fma2(aH[1][0][0], A1, w0.x); fma2(aH[1][0][1], A1, w0.y);
        fma2(aH[1][1][0], A1, w1.x); fma2(aH[1][1][1], A1, w1.y);
      }
    }
    __syncthreads();
  }

  // store H to Hs
  {
    float4 v;
    up2(aH[0][0][0], v.x, v.y); up2(aH[0][0][1], v.z, v.w);
    *(float4*)(Hs + rA * 128 + cblk * 4) = v;
    up2(aH[0][1][0], v.x, v.y); up2(aH[0][1][1], v.z, v.w);
    *(float4*)(Hs + rA * 128 + 64 + cblk * 4) = v;
    up2(aH[1][0][0], v.x, v.y); up2(aH[1][0][1], v.z, v.w);
    *(float4*)(Hs + rB * 128 + cblk * 4) = v;
    up2(aH[1][1][0], v.x, v.y); up2(aH[1][1][1], v.z, v.w);
    *(float4*)(Hs + rB * 128 + 64 + cblk * 4) = v;
  }
  // prefetch Wout into bufA (GEMM1 done with it)
  #pragma unroll
  for (int j = 0; j < 8; j++) {
    int idx = tid + j * 256;
    int r = idx >> 4, c4 = (idx & 15) * 4;
    cp16(s2u(WoutS + r * 64 + c4), p.Wout + r * 64 + c4);
  }
  cpcommit();
  __syncthreads();

  // --- eh = H @ Wpe + bpe -> zs[:,128:256] ---
  {
    u64 aE[2][2][2];
    ulonglong2 b0 = *(const ulonglong2*)(p.bpe + cblk * 4);
    ulonglong2 b1 = *(const ulonglong2*)(p.bpe + 64 + cblk * 4);
    aE[0][0][0] = b0.x; aE[0][0][1] = b0.y; aE[0][1][0] = b1.x; aE[0][1][1] = b1.y;
    aE[1][0][0] = b0.x; aE[1][0][1] = b0.y; aE[1][1][0] = b1.x; aE[1][1][1] = b1.y;
    #pragma unroll 4
    for (int k = 0; k < 128; k += 4) {
      float4 a0v = *(const float4*)(Hs + rA * 128 + k);
      float4 a1v = *(const float4*)(Hs + rB * 128 + k);
      float a0c[4] = {a0v.x, a0v.y, a0v.z, a0v.w};
      float a1c[4] = {a1v.x, a1v.y, a1v.z, a1v.w};
      #pragma unroll
      for (int s = 0; s < 4; s++) {
        u64 A0 = bc2(a0c[s]), A1 = bc2(a1c[s]);
        const float* wrow = WpeS + (k + s) * 128 + cblk * 4;
        ulonglong2 w0 = *(const ulonglong2*)(wrow);
        ulonglong2 w1 = *(const ulonglong2*)(wrow + 64);
        fma2(aE[0][0][0], A0, w0.x); fma2(aE[0][0][1], A0, w0.y);
        fma2(aE[0][1][0], A0, w1.x); fma2(aE[0][1][1], A0, w1.y);
        fma2(aE[1][0][0], A1, w0.x); fma2(aE[1][0][1], A1, w0.y);
        fma2(aE[1][1][0], A1, w1.x); fma2(aE[1][1][1], A1, w1.y);
      }
    }
    float4 v;
    up2(aE[0][0][0], v.x, v.y); up2(aE[0][0][1], v.z, v.w);
    *(float4*)(zs + rA * ZSTR + 128 + cblk * 4) = v;
    up2(aE[0][1][0], v.x, v.y); up2(aE[0][1][1], v.z, v.w);
    *(float4*)(zs + rA * ZSTR + 192 + cblk * 4) = v;
    up2(aE[1][0][0], v.x, v.y); up2(aE[1][0][1], v.z, v.w);
    *(float4*)(zs + rB * ZSTR + 128 + cblk * 4) = v;
    up2(aE[1][1][0], v.x, v.y); up2(aE[1][1][1], v.z, v.w);
    *(float4*)(zs + rB * ZSTR + 192 + cblk * 4) = v;
  }
  __syncthreads();   // eh visible; WpeS free for Wz reuse

  // --- gates: pre[32x512] = z[32x384] @ Wz + bz, chunks of 16 k ---
  const int rowg = tid >> 5;       // warp id: 8 warps x 4 rows
  const int colg = tid & 31;       // lane: 4-col chunks per gate
  const int zr = rowg * 4;

  u64 ag[4][4][2];
  #pragma unroll
  for (int q = 0; q < 4; q++) {
    ulonglong2 bb = *(const ulonglong2*)(g_bz + q * 128 + colg * 4);
    #pragma unroll
    for (int j = 0; j < 4; j++) { ag[j][q][0] = bb.x; ag[j][q][1] = bb.y; }
  }

  // prefetch gate chunk 0
  #pragma unroll
  for (int j = 0; j < 8; j++) {
    int idx = tid + j * 256;
    int r = idx >> 7, c4 = (idx & 127) * 4;
    cp16(s2u(WzS + r * 512 + c4), g_Wz + r * 512 + c4);
  }
  cpcommit();

  #pragma unroll 1
  for (int ch = 0; ch < 24; ch++) {
    if (ch < 23) {
      int nb = (ch + 1) & 1;
      int k0 = (ch + 1) * 16;
      #pragma unroll
      for (int j = 0; j < 8; j++) {
        int idx = tid + j * 256;
        int r = idx >> 7, c4 = (idx & 127) * 4;
        cp16(s2u(WzS + nb * 8192 + r * 512 + c4), g_Wz + (size_t)(k0 + r) * 512 + c4);
      }
      cpcommit();
      cpwait<1>();
    } else {
      cpwait<0>();
    }
    __syncthreads();
    const float* Wc = WzS + (ch & 1) * 8192;
    const int kb = ch * 16;
    #pragma unroll 1
    for (int kk = 0; kk < 16; kk += 4) {
      float4 z0 = *(const float4*)(zs + (zr + 0) * ZSTR + kb + kk);
      float4 z1 = *(const float4*)(zs + (zr + 1) * ZSTR + kb + kk);
      float4 z2 = *(const float4*)(zs + (zr + 2) * ZSTR + kb + kk);
      float4 z3 = *(const float4*)(zs + (zr + 3) * ZSTR + kb + kk);
      float c0a[4] = {z0.x, z0.y, z0.z, z0.w};
      float c1a[4] = {z1.x, z1.y, z1.z, z1.w};
      float c2a[4] = {z2.x, z2.y, z2.z, z2.w};
      float c3a[4] = {z3.x, z3.y, z3.z, z3.w};
      #pragma unroll
      for (int s = 0; s < 4; s++) {
        u64 A0 = bc2(c0a[s]), A1 = bc2(c1a[s]), A2 = bc2(c2a[s]), A3 = bc2(c3a[s]);
        const float* wrow = Wc + (kk + s) * 512 + colg * 4;
        #pragma unroll
        for (int q = 0; q < 4; q++) {
          ulonglong2 w = *(const ulonglong2*)(wrow + q * 128);
          fma2(ag[0][q][0], A0, w.x); fma2(ag[0][q][1], A0, w.y);
          fma2(ag[1][q][0], A1, w.x); fma2(ag[1][q][1], A1, w.y);
          fma2(ag[2][q][0], A2, w.x); fma2(ag[2][q][1], A2, w.y);
          fma2(ag[3][q][0], A3, w.x); fma2(ag[3][q][1], A3, w.y);
        }
      }
    }
    __syncthreads();
  }

  // --- pointwise LSTM (gate order q: 0=i,1=f,2=g,3=o) ---
  {
    const int rowbase = b * N_ + r0 + zr;
    #pragma unroll
    for (int j = 0; j < 4; j++) {
      float pre[4][4];
      #pragma unroll
      for (int q = 0; q < 4; q++) {
        up2(ag[j][q][0], pre[q][0], pre[q][1]);
        up2(ag[j][q][1], pre[q][2], pre[q][3]);
      }
      float* crow = g_c + (size_t)(rowbase + j) * NH_ + colg * 4;
      float4 co = *(const float4*)crow;
      float cin[4] = {co.x, co.y, co.z, co.w};
      float cn[4], hh[4];
      #pragma unroll
      for (int pp = 0; pp < 4; pp++) {
        float iv = fsgm(pre[0][pp]);
        float fv = fsgm(pre[1][pp]);
        float gv = tanhf(pre[2][pp]);
        float ov = fsgm(pre[3][pp]);
        cn[pp] = fv * cin[pp] + iv * gv;
        hh[pp] = ov * tanhf(cn[pp]);
      }
      *(float4*)crow = make_float4(cn[0], cn[1], cn[2], cn[3]);
      float4 hv = make_float4(hh[0], hh[1], hh[2], hh[3]);
      *(float4*)(hnext + (size_t)(rowbase + j) * NH_ + colg * 4) = hv;
      *(float4*)(Hs + (zr + j) * 128 + colg * 4) = hv;
    }
  }
  __syncthreads();

  // --- out[t] = out[t-1] + h @ Wout + bout ---
  {
    u64 ao[2][2];
    ulonglong2 bb = *(const ulonglong2*)(p.bout + cblk * 4);
    ao[0][0] = bb.x; ao[0][1] = bb.y; ao[1][0] = bb.x; ao[1][1] = bb.y;
    #pragma unroll 4
    for (int k = 0; k < 128; k += 4) {
      float4 a0v = *(const float4*)(Hs + rA * 128 + k);
      float4 a1v = *(const float4*)(Hs + rB * 128 + k);
      float a0c[4] = {a0v.x, a0v.y, a0v.z, a0v.w};
      float a1c[4] = {a1v.x, a1v.y, a1v.z, a1v.w};
      #pragma unroll
      for (int s = 0; s < 4; s++) {
        u64 A0 = bc2(a0c[s]), A1 = bc2(a1c[s]);
        ulonglong2 w = *(const ulonglong2*)(WoutS + (k + s) * 64 + cblk * 4);
        fma2(ao[0][0], A0, w.x); fma2(ao[0][1], A0, w.y);
        fma2(ao[1][0], A1, w.x); fma2(ao[1][1], A1, w.y);
      }
    }
    #pragma unroll
    for (int rr = 0; rr < 2; rr++) {
      int r = (rr ? rB : rA);
      size_t gb = (size_t)(b * N_ + r0 + r) * (T_ * NIN_);
      float4 prev = *(const float4*)(p.out + gb + (size_t)(t - 1) * NIN_ + cblk * 4);
      float x0, x1, x2, x3;
      up2(ao[rr][0], x0, x1); up2(ao[rr][1], x2, x3);
      *(float4*)(p.out + gb + (size_t)t * NIN_ + cblk * 4) =
          make_float4(prev.x + x0, prev.y + x1, prev.z + x2, prev.w + x3);
    }
  }
}

// ---------------- host launch ----------------
extern "C" void kernel_launch(void* const* d_in, const int* in_sizes, int n_in,
                              void* d_out, int out_size) {
  const float* X   = (const float*)d_in[0];
  const float* A   = (const float*)d_in[1];
  const float* Wse = (const float*)d_in[2];
  const float* bse = (const float*)d_in[3];
  StepP p;
  p.Wpe  = (const float*)d_in[4];  p.bpe  = (const float*)d_in[5];
  p.Wii  = (const float*)d_in[6];  p.bii  = (const float*)d_in[7];
  p.Whi  = (const float*)d_in[8];  p.bhi  = (const float*)d_in[9];
  p.Wif  = (const float*)d_in[10]; p.bif  = (const float*)d_in[11];
  p.Whf  = (const float*)d_in[12]; p.bhf  = (const float*)d_in[13];
  p.Wig  = (const float*)d_in[14]; p.big  = (const float*)d_in[15];
  p.Whg  = (const float*)d_in[16]; p.bhg  = (const float*)d_in[17];
  p.Wio  = (const float*)d_in[18]; p.bio  = (const float*)d_in[19];
  p.Who  = (const float*)d_in[20]; p.bho  = (const float*)d_in[21];
  p.Wout = (const float*)d_in[22]; p.bout = (const float*)d_in[23];
  p.out  = (float*)d_out;

  const int SMEM = SM_TOTF * 4;  // 214,016 B
  cudaFuncSetAttribute(k_step, cudaFuncAttributeMaxDynamicSharedMemorySize, SMEM);

  k_dinv<<<ROWS_, 128>>>(A);
  k_an<<<2048, 256>>>(A);
  k_fuse<<<768, 256>>>(p);
  k_init<<<2048, 256>>>(X, Wse, bse, p.out);
  for (int t = 1; t < T_; t++) {
    k_step<<<dim3(N_ / 32, B_), 256, SMEM>>>(p, t);
  }
}